// round 10
// baseline (speedup 1.0000x reference)
#include <cuda_runtime.h>
#include <cuda_bf16.h>
#include <math.h>

#define NN    10000
#define EE    160000
#define FEAT  768           // 64*12
#define TOTC  120000        // NN*12 gemm columns
#define PADR  (NN * 14)     // padded rows
typedef unsigned long long ull;
typedef unsigned u32;

// ---------------- scratch (device globals; no allocation) ----------------
__device__ float g_bufA[NN * FEAT];
__device__ float g_bufB[NN * FEAT];
__device__ __nv_bfloat16 g_xh32[PADR * 32];  // padded C=32 input images
__device__ __nv_bfloat16 g_xl32[PADR * 32];
__device__ __nv_bfloat16 g_h1[PADR * 64];    // padded C=64 images
__device__ __nv_bfloat16 g_l1[PADR * 64];
__device__ __nv_bfloat16 g_h2[PADR * 64];
__device__ __nv_bfloat16 g_l2[PADR * 64];
__device__ float g_deg[NN];
__device__ float g_dis[NN];
__device__ int   g_cnt[NN];
__device__ int   g_rowptr[NN + 1];
__device__ ull   g_edge[EE];
__device__ u32   g_wfrag[86016];   // frag-ordered hi/lo weights, 4 layers

// ---------------- helpers ----------------
__device__ __forceinline__ u32 smem_u32(const void* p) {
    u32 a;
    asm("{ .reg .u64 t; cvta.to.shared.u64 t, %1; cvt.u32.u64 %0, t; }" : "=r"(a) : "l"(p));
    return a;
}
__device__ __forceinline__ u32 pack_bf2(float a, float b) {   // low half = a, high = b
    u32 r;
    asm("cvt.rn.satfinite.bf16x2.f32 %0, %1, %2;" : "=r"(r) : "f"(b), "f"(a));
    return r;
}
__device__ __forceinline__ void ldsm_x4(u32& r0, u32& r1, u32& r2, u32& r3, u32 a) {
    asm volatile("ldmatrix.sync.aligned.m8n8.x4.shared.b16 {%0,%1,%2,%3}, [%4];"
                 : "=r"(r0), "=r"(r1), "=r"(r2), "=r"(r3) : "r"(a));
}
__device__ __forceinline__ void mma16816(float& d0, float& d1, float& d2, float& d3,
                                         u32 a0, u32 a1, u32 a2, u32 a3, u32 b0, u32 b1) {
    asm volatile("mma.sync.aligned.m16n8k16.row.col.f32.bf16.bf16.f32 "
                 "{%0,%1,%2,%3}, {%4,%5,%6,%7}, {%8,%9}, {%0,%1,%2,%3};"
                 : "+f"(d0), "+f"(d1), "+f"(d2), "+f"(d3)
                 : "r"(a0), "r"(a1), "r"(a2), "r"(a3), "r"(b0), "r"(b1));
}
__device__ __forceinline__ void cp_async16(u32 dst, const void* src, bool v) {
    asm volatile("cp.async.cg.shared.global [%0], [%1], 16, %2;"
                 :: "r"(dst), "l"(src), "r"(v ? 16 : 0));
}
#define CP_COMMIT() asm volatile("cp.async.commit_group;" ::: "memory")
#define CP_WAIT1()  asm volatile("cp.async.wait_group 1;" ::: "memory")
#define CP_WAIT0()  asm volatile("cp.async.wait_group 0;" ::: "memory")

// ---------------- zero: deg/cnt + all pad rows (re-run every launch) ----------
__global__ void zero_kernel() {
    int i = blockIdx.x * blockDim.x + threadIdx.x;
    if (i < NN) { g_deg[i] = 0.f; g_cnt[i] = 0; }
    __nv_bfloat16 z = __float2bfloat16(0.f);
    if (i < 640000) {                       // stride-32 pad rows, 2 images
        int c = i & 31, r = (i >> 5) & 1, n = i >> 6;
        size_t idx = ((size_t)n * 14 + (r ? 13 : 0)) * 32 + c;
        g_xh32[idx] = z; g_xl32[idx] = z;
    } else if (i < 1920000) {               // stride-64 pad rows, 4 images
        int j = i - 640000;
        int c = j & 63, r = (j >> 6) & 1, n = j >> 7;
        size_t idx = ((size_t)n * 14 + (r ? 13 : 0)) * 64 + c;
        g_h1[idx] = z; g_l1[idx] = z; g_h2[idx] = z; g_l2[idx] = z;
    }
}

__global__ void hist_kernel(const int* __restrict__ ei, const float* __restrict__ ew) {
    int e = blockIdx.x * blockDim.x + threadIdx.x;
    if (e < EE) {
        int d = ei[EE + e];
        atomicAdd(&g_deg[d], ew[e]);
        atomicAdd(&g_cnt[d], 1);
    }
}
__global__ void scan_kernel() {
    __shared__ int sd[1024];
    int tid = threadIdx.x;
    int offset = 0;
    for (int base = 0; base < NN; base += 1024) {
        int i = base + tid;
        int v = (i < NN) ? g_cnt[i] : 0;
        if (i < NN) { g_dis[i] = rsqrtf(g_deg[i] + 1.0f); g_cnt[i] = 0; }
        sd[tid] = v;
        __syncthreads();
        for (int s = 1; s < 1024; s <<= 1) {
            int t = (tid >= s) ? sd[tid - s] : 0;
            __syncthreads();
            sd[tid] += t;
            __syncthreads();
        }
        if (i < NN) g_rowptr[i] = offset + sd[tid] - v;
        offset += sd[1023];
        __syncthreads();
    }
    if (tid == 0) g_rowptr[NN] = offset;
}
__global__ void scatter_kernel(const int* __restrict__ ei, const float* __restrict__ ew) {
    int e = blockIdx.x * blockDim.x + threadIdx.x;
    if (e < EE) {
        int d = ei[EE + e];
        int s = ei[e];
        int pos = g_rowptr[d] + atomicAdd(&g_cnt[d], 1);
        float coef = g_dis[s] * ew[e] * g_dis[d];
        g_edge[pos] = ((ull)__float_as_uint(coef) << 32) | (unsigned)s;
    }
}

// ---------------- weight prepack -> mma fragment order ----------------
__global__ void prep_w_kernel(const float* __restrict__ w0, const float* __restrict__ w1,
                              const float* __restrict__ w2, const float* __restrict__ w3) {
    int v = blockIdx.x * 256 + threadIdx.x;
    if (v >= 21504) return;
    const float* w; int C, off;
    if (v < 3072)       { w = w0; C = 32; off = 0; }
    else if (v < 9216)  { w = w1; C = 64; off = 3072; }
    else if (v < 15360) { w = w2; C = 64; off = 9216; }
    else                { w = w3; C = 64; off = 15360; }
    int r = v - off;
    int KS = C / 16;
    int lane = r & 31; r >>= 5;
    int wid = r & 7;  r >>= 3;
    int ks = r % KS;  r /= KS;
    int tap = r % 3;  r /= 3;
    int s = r;
    u32 o4[4];
#pragma unroll
    for (int rr = 0; rr < 4; rr++) {
        float vv[2];
#pragma unroll
        for (int b = 0; b < 2; b++) {
            int m_local = (rr & 1) * 8 + (lane >> 2);
            int k = (rr >> 1) * 8 + (lane & 3) * 2 + b;
            int hh = wid * 8 + (m_local & 7);
            int orig = (m_local < 8) ? hh : 64 + hh;
            int c = ks * 16 + k;
            float val = w[(size_t)orig * C * 3 + c * 3 + tap];
            float hi = __bfloat162float(__float2bfloat16(val));
            vv[b] = (s == 0) ? hi : (val - hi);
        }
        o4[rr] = pack_bf2(vv[0], vv[1]);
    }
    ((uint4*)g_wfrag)[v] = make_uint4(o4[0], o4[1], o4[2], o4[3]);
}

// ---------------- input transpose + split: [n][32][12] -> padded [n][14][32] ----
__global__ void transpose_x_kernel(const float* __restrict__ in) {
    int i = blockIdx.x * 256 + threadIdx.x;
    if (i < NN * 384) {
        int c = i & 31;
        int t = (i >> 5) % 12;
        int n = i / 384;
        float v = in[n * 384 + c * 12 + t];
        __nv_bfloat16 h = __float2bfloat16(v);
        size_t idx = ((size_t)n * 14 + 1 + t) * 32 + c;
        g_xh32[idx] = h;
        g_xl32[idx] = __float2bfloat16(v - __bfloat162float(h));
    }
}

// ---------------- tensor-core gated temporal conv (padded, no masks) ----------
// xh/xl: padded bf16 [PADR][C]; out fp32 [col][64] unpadded, or padded bf16 hi/lo
template <int C, bool OUTBF>
__global__ void __launch_bounds__(256, 2)
tconv_mma_kernel(const __nv_bfloat16* __restrict__ xh, const __nv_bfloat16* __restrict__ xl,
                 const uint4* __restrict__ wf, const float* __restrict__ bias,
                 float* __restrict__ outf,
                 __nv_bfloat16* __restrict__ oh, __nv_bfloat16* __restrict__ ol) {
    const int KS = C / 16;
    const int PAIRS = KS / 2;
    const int WST = C + 8;                 // smem row stride (bf16)
    const int ROWS = 78;                   // padded window rows per tile
    const int BUFSZ = 2 * ROWS * WST;      // hi + lo, bf16 elems
    const int CHK = C / 8;                 // 16B chunks per row
    const int NCH = ROWS * CHK;
    extern __shared__ __align__(16) __nv_bfloat16 sw[];
    const int tid = threadIdx.x;
    const int lane = tid & 31, wid = tid >> 5;
    u32 sb = smem_u32(sw);

    float bP = bias[wid * 8 + (lane >> 2)];
    float bQ = bias[64 + wid * 8 + (lane >> 2)];
    const int h = wid * 8 + (lane >> 2);
    const int lc = lane & 3;
    const int NT = TOTC / 64;

    // stage one tile's padded hi+lo window (contiguous padded rows)
    auto stage = [&](int t, int bufsel) {
        int base = t * 64;
        int pstart = base + 2 * (base / 12);   // pad(base) - 1
        for (int i = tid; i < 2 * NCH; i += 256) {
            int img = (i >= NCH);
            int j = i - img * NCH;
            int row = j / CHK, ch = j - row * CHK;
            int g = pstart + row;
            bool valid = (g < PADR);
            size_t gg = valid ? (size_t)g : 0;
            const __nv_bfloat16* src = (img ? xl : xh) + gg * C + ch * 8;
            u32 dst = sb + (u32)((bufsel * BUFSZ + (img * ROWS + row) * WST) * 2 + ch * 16);
            cp_async16(dst, src, valid);
        }
    };

    int t0 = blockIdx.x;
    if (t0 < NT) stage(t0, 0);
    CP_COMMIT();
    int sel = 0;

    for (int tile = t0; tile < NT; tile += gridDim.x) {
        int base = tile * 64;
        int pstart = base + 2 * (base / 12);
        int nxt = tile + gridDim.x;
        if (nxt < NT) {
            stage(nxt, sel ^ 1);
            CP_COMMIT();
            CP_WAIT1();
        } else {
            CP_WAIT0();
        }
        __syncthreads();

        // per-thread padded row base for each n-subtile (own-lane ldmatrix address)
        int prow[8];
#pragma unroll
        for (int ns = 0; ns < 8; ns++) {
            int col = base + ns * 8 + (lane & 7);
            prow[ns] = col + 2 * (col / 12) - pstart;   // pad(col)-1-pstart
        }

        float d[8][4];
#pragma unroll
        for (int ns = 0; ns < 8; ns++) { d[ns][0] = d[ns][1] = d[ns][2] = d[ns][3] = 0.f; }

        u32 bufbase = sb + (u32)(sel * BUFSZ * 2);
        const int kksel = ((lane >> 3) & 3) * 8;

#pragma unroll
        for (int pair = 0; pair < PAIRS; pair++) {
            uint4 AH[3][2], AL[3][2];
#pragma unroll
            for (int tap = 0; tap < 3; tap++)
#pragma unroll
                for (int k2 = 0; k2 < 2; k2++) {
                    AH[tap][k2] = wf[((tap * KS + pair * 2 + k2) * 8 + wid) * 32 + lane];
                    AL[tap][k2] = wf[(((3 + tap) * KS + pair * 2 + k2) * 8 + wid) * 32 + lane];
                }
            int kk = pair * 32 + kksel;
#pragma unroll
            for (int ns = 0; ns < 8; ns++) {
#pragma unroll
                for (int tap = 0; tap < 3; tap++) {
                    u32 a = bufbase + (u32)(((prow[ns] + tap) * WST + kk) * 2);
                    u32 b0, b1, b2, b3, l0, l1, l2, l3;
                    ldsm_x4(b0, b1, b2, b3, a);
                    ldsm_x4(l0, l1, l2, l3, a + (u32)(ROWS * WST * 2));
                    mma16816(d[ns][0], d[ns][1], d[ns][2], d[ns][3],
                             AH[tap][0].x, AH[tap][0].y, AH[tap][0].z, AH[tap][0].w, b0, b1);
                    mma16816(d[ns][0], d[ns][1], d[ns][2], d[ns][3],
                             AH[tap][0].x, AH[tap][0].y, AH[tap][0].z, AH[tap][0].w, l0, l1);
                    mma16816(d[ns][0], d[ns][1], d[ns][2], d[ns][3],
                             AL[tap][0].x, AL[tap][0].y, AL[tap][0].z, AL[tap][0].w, b0, b1);
                    mma16816(d[ns][0], d[ns][1], d[ns][2], d[ns][3],
                             AH[tap][1].x, AH[tap][1].y, AH[tap][1].z, AH[tap][1].w, b2, b3);
                    mma16816(d[ns][0], d[ns][1], d[ns][2], d[ns][3],
                             AH[tap][1].x, AH[tap][1].y, AH[tap][1].z, AH[tap][1].w, l2, l3);
                    mma16816(d[ns][0], d[ns][1], d[ns][2], d[ns][3],
                             AL[tap][1].x, AL[tap][1].y, AL[tap][1].z, AL[tap][1].w, b2, b3);
                }
            }
        }

        // ---- epilogue: gate in-register (c0,c1)=P, (c2,c3)=Q of same h ----
#pragma unroll
        for (int ns = 0; ns < 8; ns++) {
            int col0 = base + ns * 8 + 2 * lc;
            float s2 = 1.f / (1.f + __expf(-(d[ns][2] + bQ)));
            float s3 = 1.f / (1.f + __expf(-(d[ns][3] + bQ)));
            float v0 = (d[ns][0] + bP) * s2;
            float v1 = (d[ns][1] + bP) * s3;
            if (OUTBF) {
                int p0 = col0 + 2 * (col0 / 12) + 1;
                int p1 = (col0 + 1) + 2 * ((col0 + 1) / 12) + 1;
                __nv_bfloat16 h0 = __float2bfloat16(v0);
                __nv_bfloat16 h1 = __float2bfloat16(v1);
                oh[(size_t)p0 * 64 + h] = h0;
                ol[(size_t)p0 * 64 + h] = __float2bfloat16(v0 - __bfloat162float(h0));
                oh[(size_t)p1 * 64 + h] = h1;
                ol[(size_t)p1 * 64 + h] = __float2bfloat16(v1 - __bfloat162float(h1));
            } else {
                outf[(size_t)col0 * 64 + h]       = v0;
                outf[(size_t)(col0 + 1) * 64 + h] = v1;
            }
        }
        __syncthreads();
        sel ^= 1;
    }
}

// ---------------- fused GCN (in: fp32 [n][t][c]; out: padded bf16 hi/lo) -------
__global__ void __launch_bounds__(192)
gcn_fused_kernel(const float* __restrict__ in,
                 __nv_bfloat16* __restrict__ oh, __nv_bfloat16* __restrict__ ol,
                 const float* __restrict__ W, const float* __restrict__ bias) {
    __shared__ __align__(16) float xs[768];
    __shared__ float Ws[64 * 65];
    int n = blockIdx.x, tid = threadIdx.x;

    for (int gi = tid; gi < 4096; gi += 192) {
        int o = gi >> 6, c = gi & 63;
        Ws[c * 65 + o] = W[gi];
    }

    float d = g_dis[n];
    float d2 = d * d;
    float4 acc = ((const float4*)(in + (size_t)n * FEAT))[tid];
    acc.x *= d2; acc.y *= d2; acc.z *= d2; acc.w *= d2;

    int e = g_rowptr[n], e1 = g_rowptr[n + 1];
    for (; e + 4 <= e1; e += 4) {
        ull p0 = g_edge[e], p1 = g_edge[e + 1], p2 = g_edge[e + 2], p3 = g_edge[e + 3];
        int s0 = (int)(unsigned)p0, s1 = (int)(unsigned)p1;
        int s2 = (int)(unsigned)p2, s3 = (int)(unsigned)p3;
        float c0 = __uint_as_float((unsigned)(p0 >> 32));
        float c1 = __uint_as_float((unsigned)(p1 >> 32));
        float c2 = __uint_as_float((unsigned)(p2 >> 32));
        float c3 = __uint_as_float((unsigned)(p3 >> 32));
        float4 v0 = ((const float4*)(in + (size_t)s0 * FEAT))[tid];
        float4 v1 = ((const float4*)(in + (size_t)s1 * FEAT))[tid];
        float4 v2 = ((const float4*)(in + (size_t)s2 * FEAT))[tid];
        float4 v3 = ((const float4*)(in + (size_t)s3 * FEAT))[tid];
        acc.x += c0 * v0.x + c1 * v1.x + c2 * v2.x + c3 * v3.x;
        acc.y += c0 * v0.y + c1 * v1.y + c2 * v2.y + c3 * v3.y;
        acc.z += c0 * v0.z + c1 * v1.z + c2 * v2.z + c3 * v3.z;
        acc.w += c0 * v0.w + c1 * v1.w + c2 * v2.w + c3 * v3.w;
    }
    for (; e < e1; e++) {
        ull p = g_edge[e];
        int s = (int)(unsigned)p;
        float cf = __uint_as_float((unsigned)(p >> 32));
        float4 v = ((const float4*)(in + (size_t)s * FEAT))[tid];
        acc.x += cf * v.x; acc.y += cf * v.y; acc.z += cf * v.z; acc.w += cf * v.w;
    }
    ((float4*)xs)[tid] = acc;
    __syncthreads();

    int o = tid & 63, tg = tid >> 6;
    float a0 = 0.f, a1 = 0.f, a2 = 0.f, a3 = 0.f;
#pragma unroll 8
    for (int c = 0; c < 64; c++) {
        float wv = Ws[c * 65 + o];
        const float* xp = xs + c;
        a0 += wv * xp[(tg * 4 + 0) * 64];
        a1 += wv * xp[(tg * 4 + 1) * 64];
        a2 += wv * xp[(tg * 4 + 2) * 64];
        a3 += wv * xp[(tg * 4 + 3) * 64];
    }
    float bv = bias[o];
    float rr[4] = {fmaxf(a0 + bv, 0.f), fmaxf(a1 + bv, 0.f),
                   fmaxf(a2 + bv, 0.f), fmaxf(a3 + bv, 0.f)};
#pragma unroll
    for (int i = 0; i < 4; i++) {
        size_t idx = ((size_t)n * 14 + 1 + tg * 4 + i) * 64 + o;
        __nv_bfloat16 hv = __float2bfloat16(rr[i]);
        oh[idx] = hv;
        ol[idx] = __float2bfloat16(rr[i] - __bfloat162float(hv));
    }
}

// ---------------- final conv (layout [n][t][c]) ----------------
__global__ void fin_kernel(const float* __restrict__ in, const float* __restrict__ w,
                           const float* __restrict__ b, float* __restrict__ out) {
    extern __shared__ float smf[];
    float* wt = smf;              // 12 rows, stride 772, reindexed [t*64+h]
    float* xt = smf + 12 * 772;   // 16 nodes, stride 772
    int tid = threadIdx.x;        // 192
    for (int i = tid; i < 12 * 768; i += 192) {
        int o = i / 768, r = i - o * 768;
        int t = r >> 6, hh = r & 63;
        wt[o * 772 + r] = w[o * 768 + hh * 12 + t];
    }
    int n0 = blockIdx.x * 16;
    for (int gi = tid; gi < 16 * 192; gi += 192) {
        int node = gi / 192, j = gi - node * 192;
        ((float4*)(xt + node * 772))[j] =
            ((const float4*)(in + (size_t)(n0 + node) * FEAT))[j];
    }
    __syncthreads();
    int node = tid / 12, o = tid - node * 12;
    const float* wr = wt + o * 772;
    const float* xr = xt + node * 772;
    float acc = 0.f;
#pragma unroll 4
    for (int j = 0; j < 192; j++) {
        float4 a = ((const float4*)wr)[j];
        float4 v = ((const float4*)xr)[j];
        acc += a.x * v.x + a.y * v.y + a.z * v.z + a.w * v.w;
    }
    out[(size_t)(n0 + node) * 12 + o] = acc + b[o];
}

// ---------------- launch ----------------
extern "C" void kernel_launch(void* const* d_in, const int* in_sizes, int n_in,
                              void* d_out, int out_size) {
    const float* x      = (const float*)d_in[0];
    const int*   ei     = (const int*)d_in[1];
    const float* ew     = (const float*)d_in[2];
    const float* tc1a_w = (const float*)d_in[3];
    const float* tc1a_b = (const float*)d_in[4];
    const float* gc1_w  = (const float*)d_in[5];
    const float* gc1_b  = (const float*)d_in[6];
    const float* tc1b_w = (const float*)d_in[7];
    const float* tc1b_b = (const float*)d_in[8];
    const float* tc2a_w = (const float*)d_in[9];
    const float* tc2a_b = (const float*)d_in[10];
    const float* gc2_w  = (const float*)d_in[11];
    const float* gc2_b  = (const float*)d_in[12];
    const float* tc2b_w = (const float*)d_in[13];
    const float* tc2b_b = (const float*)d_in[14];
    const float* fin_w  = (const float*)d_in[15];
    const float* fin_b  = (const float*)d_in[16];
    float* out = (float*)d_out;

    float *pA, *pB; uint4* pW;
    __nv_bfloat16 *pXH, *pXL, *pH1, *pL1, *pH2, *pL2;
    cudaGetSymbolAddress((void**)&pA, g_bufA);
    cudaGetSymbolAddress((void**)&pB, g_bufB);
    cudaGetSymbolAddress((void**)&pW, g_wfrag);
    cudaGetSymbolAddress((void**)&pXH, g_xh32);
    cudaGetSymbolAddress((void**)&pXL, g_xl32);
    cudaGetSymbolAddress((void**)&pH1, g_h1);
    cudaGetSymbolAddress((void**)&pL1, g_l1);
    cudaGetSymbolAddress((void**)&pH2, g_h2);
    cudaGetSymbolAddress((void**)&pL2, g_l2);

    const int smem32 = 2 * 2 * 78 * 40 * 2;    // 24960
    const int smem64 = 2 * 2 * 78 * 72 * 2;    // 44928
    const int smemF  = (12 + 16) * 772 * 4;
    cudaFuncSetAttribute(fin_kernel, cudaFuncAttributeMaxDynamicSharedMemorySize, smemF);
    cudaFuncSetAttribute((const void*)tconv_mma_kernel<64, true>,
                         cudaFuncAttributeMaxDynamicSharedMemorySize, smem64);
    cudaFuncSetAttribute((const void*)tconv_mma_kernel<64, false>,
                         cudaFuncAttributeMaxDynamicSharedMemorySize, smem64);
    cudaFuncSetAttribute((const void*)tconv_mma_kernel<32, false>,
                         cudaFuncAttributeMaxDynamicSharedMemorySize, smem32);

    // order: big mma kernel in ncu capture slot (#4)
    zero_kernel<<<(1920000 + 255) / 256, 256>>>();
    prep_w_kernel<<<(21504 + 255) / 256, 256>>>(tc1a_w, tc1b_w, tc2a_w, tc2b_w);
    transpose_x_kernel<<<(NN * 384 + 255) / 256, 256>>>(x);
    // tc1a: (XH,XL) -> A fp32
    tconv_mma_kernel<32, false><<<296, 256, smem32>>>(pXH, pXL, pW, tc1a_b, pA, 0, 0);
    hist_kernel<<<(EE + 255) / 256, 256>>>(ei, ew);
    scan_kernel<<<1, 1024>>>();
    scatter_kernel<<<(EE + 255) / 256, 256>>>(ei, ew);
    // gcn1: A -> (H1,L1) padded
    gcn_fused_kernel<<<NN, 192>>>(pA, pH1, pL1, gc1_w, gc1_b);
    // tc1b: (H1,L1) -> (H2,L2) padded
    tconv_mma_kernel<64, true><<<296, 256, smem64>>>(pH1, pL1, pW + 3072, tc1b_b, 0, pH2, pL2);
    // tc2a: (H2,L2) -> A fp32
    tconv_mma_kernel<64, false><<<296, 256, smem64>>>(pH2, pL2, pW + 9216, tc2a_b, pA, 0, 0);
    // gcn2: A -> (H1,L1)
    gcn_fused_kernel<<<NN, 192>>>(pA, pH1, pL1, gc2_w, gc2_b);
    // tc2b: (H1,L1) -> B fp32
    tconv_mma_kernel<64, false><<<296, 256, smem64>>>(pH1, pL1, pW + 15360, tc2b_b, pB, 0, 0);
    // fin: B -> out
    fin_kernel<<<NN / 16, 192, smemF>>>(pB, fin_w, fin_b, out);
}

// round 11
// speedup vs baseline: 1.0765x; 1.0765x over previous
#include <cuda_runtime.h>
#include <cuda_bf16.h>
#include <math.h>

#define NN    10000
#define EE    160000
#define FEAT  768           // 64*12
#define TOTC  120000        // NN*12 gemm columns
typedef unsigned long long ull;
typedef unsigned u32;

// ---------------- scratch (device globals; no allocation) ----------------
__device__ float g_bufA[NN * FEAT];
__device__ float g_bufB[NN * FEAT];
__device__ __nv_bfloat16 g_h1[NN * FEAT];
__device__ __nv_bfloat16 g_l1[NN * FEAT];
__device__ __nv_bfloat16 g_h2[NN * FEAT];
__device__ __nv_bfloat16 g_l2[NN * FEAT];
__device__ float g_deg[NN];
__device__ float g_dis[NN];
__device__ int   g_cnt[NN];
__device__ int   g_rowptr[NN + 1];
__device__ ull   g_edge[EE];
__device__ u32   g_wfrag[86016];   // frag-ordered hi/lo weights, 4 layers

// ---------------- helpers ----------------
__device__ __forceinline__ u32 smem_u32(const void* p) {
    u32 a;
    asm("{ .reg .u64 t; cvta.to.shared.u64 t, %1; cvt.u32.u64 %0, t; }" : "=r"(a) : "l"(p));
    return a;
}
__device__ __forceinline__ u32 pack_bf2(float a, float b) {   // low half = a, high = b
    u32 r;
    asm("cvt.rn.satfinite.bf16x2.f32 %0, %1, %2;" : "=r"(r) : "f"(b), "f"(a));
    return r;
}
__device__ __forceinline__ void ldsm_x4(u32& r0, u32& r1, u32& r2, u32& r3, u32 a) {
    asm volatile("ldmatrix.sync.aligned.m8n8.x4.shared.b16 {%0,%1,%2,%3}, [%4];"
                 : "=r"(r0), "=r"(r1), "=r"(r2), "=r"(r3) : "r"(a));
}
__device__ __forceinline__ void mma16816(float& d0, float& d1, float& d2, float& d3,
                                         u32 a0, u32 a1, u32 a2, u32 a3, u32 b0, u32 b1) {
    asm volatile("mma.sync.aligned.m16n8k16.row.col.f32.bf16.bf16.f32 "
                 "{%0,%1,%2,%3}, {%4,%5,%6,%7}, {%8,%9}, {%0,%1,%2,%3};"
                 : "+f"(d0), "+f"(d1), "+f"(d2), "+f"(d3)
                 : "r"(a0), "r"(a1), "r"(a2), "r"(a3), "r"(b0), "r"(b1));
}
__device__ __forceinline__ void cp_async16(u32 dst, const void* src, bool v) {
    asm volatile("cp.async.cg.shared.global [%0], [%1], 16, %2;"
                 :: "r"(dst), "l"(src), "r"(v ? 16 : 0));
}
#define CP_COMMIT() asm volatile("cp.async.commit_group;" ::: "memory")
#define CP_WAIT1()  asm volatile("cp.async.wait_group 1;" ::: "memory")
#define CP_WAIT0()  asm volatile("cp.async.wait_group 0;" ::: "memory")

// ---------------- CSR build ----------------
__global__ void zero_kernel() {
    int i = blockIdx.x * blockDim.x + threadIdx.x;
    if (i < NN) { g_deg[i] = 0.f; g_cnt[i] = 0; }
}
__global__ void hist_kernel(const int* __restrict__ ei, const float* __restrict__ ew) {
    int e = blockIdx.x * blockDim.x + threadIdx.x;
    if (e < EE) {
        int d = ei[EE + e];
        atomicAdd(&g_deg[d], ew[e]);
        atomicAdd(&g_cnt[d], 1);
    }
}
// single block, warp-shuffle scan (3 barriers per 1024-chunk)
__global__ void scan_kernel() {
    __shared__ int wsum[32];
    __shared__ int choff;
    int tid = threadIdx.x;
    int lane = tid & 31, w = tid >> 5;
    if (tid == 0) choff = 0;
    __syncthreads();
    for (int base = 0; base < NN; base += 1024) {
        int i = base + tid;
        int v = (i < NN) ? g_cnt[i] : 0;
        if (i < NN) { g_dis[i] = rsqrtf(g_deg[i] + 1.0f); g_cnt[i] = 0; }
        int s = v;
#pragma unroll
        for (int d = 1; d < 32; d <<= 1) {
            int t = __shfl_up_sync(~0u, s, d);
            if (lane >= d) s += t;
        }
        if (lane == 31) wsum[w] = s;
        __syncthreads();
        if (w == 0) {
            int ws = wsum[lane];
#pragma unroll
            for (int d = 1; d < 32; d <<= 1) {
                int t = __shfl_up_sync(~0u, ws, d);
                if (lane >= d) ws += t;
            }
            wsum[lane] = ws;
        }
        __syncthreads();
        int off = choff + ((w > 0) ? wsum[w - 1] : 0);
        int total = wsum[31];
        if (i < NN) g_rowptr[i] = off + s - v;
        __syncthreads();
        if (tid == 0) choff += total;
        __syncthreads();
    }
    if (tid == 0) g_rowptr[NN] = choff;
}
__global__ void scatter_kernel(const int* __restrict__ ei, const float* __restrict__ ew) {
    int e = blockIdx.x * blockDim.x + threadIdx.x;
    if (e < EE) {
        int d = ei[EE + e];
        int s = ei[e];
        int pos = g_rowptr[d] + atomicAdd(&g_cnt[d], 1);
        float coef = g_dis[s] * ew[e] * g_dis[d];
        g_edge[pos] = ((ull)__float_as_uint(coef) << 32) | (unsigned)s;
    }
}

// ---------------- weight prepack -> mma fragment order ----------------
__global__ void prep_w_kernel(const float* __restrict__ w0, const float* __restrict__ w1,
                              const float* __restrict__ w2, const float* __restrict__ w3) {
    int v = blockIdx.x * 256 + threadIdx.x;
    if (v >= 21504) return;
    const float* w; int C, off;
    if (v < 3072)       { w = w0; C = 32; off = 0; }
    else if (v < 9216)  { w = w1; C = 64; off = 3072; }
    else if (v < 15360) { w = w2; C = 64; off = 9216; }
    else                { w = w3; C = 64; off = 15360; }
    int r = v - off;
    int KS = C / 16;
    int lane = r & 31; r >>= 5;
    int wid = r & 7;  r >>= 3;
    int ks = r % KS;  r /= KS;
    int tap = r % 3;  r /= 3;
    int s = r;
    u32 o4[4];
#pragma unroll
    for (int rr = 0; rr < 4; rr++) {
        float vv[2];
#pragma unroll
        for (int b = 0; b < 2; b++) {
            int m_local = (rr & 1) * 8 + (lane >> 2);
            int k = (rr >> 1) * 8 + (lane & 3) * 2 + b;
            int hh = wid * 8 + (m_local & 7);
            int orig = (m_local < 8) ? hh : 64 + hh;
            int c = ks * 16 + k;
            float val = w[(size_t)orig * C * 3 + c * 3 + tap];
            float hi = __bfloat162float(__float2bfloat16(val));
            vv[b] = (s == 0) ? hi : (val - hi);
        }
        o4[rr] = pack_bf2(vv[0], vv[1]);
    }
    ((uint4*)g_wfrag)[v] = make_uint4(o4[0], o4[1], o4[2], o4[3]);
}

// ---------------- input transpose + split: [n][32][12] -> hi/lo [n][12][32] ----
__global__ void transpose_x_kernel(const float* __restrict__ in,
                                   __nv_bfloat16* __restrict__ oh,
                                   __nv_bfloat16* __restrict__ ol) {
    int i = blockIdx.x * 256 + threadIdx.x;
    if (i < NN * 384) {
        int c = i & 31;
        int t = (i >> 5) % 12;
        int n = i / 384;
        float v = in[n * 384 + c * 12 + t];
        __nv_bfloat16 h = __float2bfloat16(v);
        oh[i] = h;
        ol[i] = __float2bfloat16(v - __bfloat162float(h));
    }
}

// ---------------- tensor-core gated temporal conv, cp.async double-buffered ----
template <int C, bool OUTBF>
__global__ void __launch_bounds__(256, 2)
tconv_mma_kernel(const __nv_bfloat16* __restrict__ xh, const __nv_bfloat16* __restrict__ xl,
                 const uint4* __restrict__ wf, const float* __restrict__ bias,
                 float* __restrict__ outf,
                 __nv_bfloat16* __restrict__ oh, __nv_bfloat16* __restrict__ ol) {
    const int KS = C / 16;
    const int PAIRS = KS / 2;
    const int WST = C + 8;                 // smem row stride (bf16)
    const int BUFSZ = 132 * WST;           // one buffer, bf16 elems
    const int CHK = C / 8;                 // 16B chunks per row
    const int NCH = 66 * CHK;
    extern __shared__ __align__(16) __nv_bfloat16 sw[];
    const int tid = threadIdx.x;
    const int lane = tid & 31, wid = tid >> 5;
    u32 sb = smem_u32(sw);

    float bP = bias[wid * 8 + (lane >> 2)];
    float bQ = bias[64 + wid * 8 + (lane >> 2)];
    const int h = wid * 8 + (lane >> 2);
    const int lc = lane & 3;
    const int lq = lane >> 2;
    const int NT = TOTC / 64;

    auto stage = [&](int t, int bufsel) {
        int base = t * 64;
        for (int i = tid; i < 2 * NCH; i += 256) {
            int img = (i >= NCH);
            int j = i - img * NCH;
            int row = j / CHK, ch = j - row * CHK;
            int col = base - 1 + row;
            bool valid = (col >= 0 && col < TOTC);
            size_t cc = valid ? (size_t)col : 0;
            const __nv_bfloat16* src = (img ? xl : xh) + cc * C + ch * 8;
            u32 dst = sb + (u32)((bufsel * BUFSZ + (img * 66 + row) * WST) * 2 + ch * 16);
            cp_async16(dst, src, valid);
        }
    };

    int t0 = blockIdx.x;
    if (t0 < NT) stage(t0, 0);
    CP_COMMIT();
    int sel = 0;

    for (int tile = t0; tile < NT; tile += gridDim.x) {
        int base = tile * 64;
        int nxt = tile + gridDim.x;
        if (nxt < NT) {
            stage(nxt, sel ^ 1);
            CP_COMMIT();
            CP_WAIT1();
        } else {
            CP_WAIT0();
        }
        __syncthreads();

        int m0[8], m2[8];
#pragma unroll
        for (int ns = 0; ns < 8; ns++) {
            int tm = (base + ns * 8 + lq) % 12;
            m0[ns] = (tm == 0);
            m2[ns] = (tm == 11);
        }

        float d[8][4];
#pragma unroll
        for (int ns = 0; ns < 8; ns++) { d[ns][0] = d[ns][1] = d[ns][2] = d[ns][3] = 0.f; }

        u32 bufbase = sb + (u32)(sel * BUFSZ * 2);

#pragma unroll
        for (int pair = 0; pair < PAIRS; pair++) {
            uint4 AH[3][2], AL[3][2];
#pragma unroll
            for (int tap = 0; tap < 3; tap++)
#pragma unroll
                for (int k2 = 0; k2 < 2; k2++) {
                    AH[tap][k2] = wf[((tap * KS + pair * 2 + k2) * 8 + wid) * 32 + lane];
                    AL[tap][k2] = wf[(((3 + tap) * KS + pair * 2 + k2) * 8 + wid) * 32 + lane];
                }
#pragma unroll
            for (int ns = 0; ns < 8; ns++) {
#pragma unroll
                for (int tap = 0; tap < 3; tap++) {
                    int row = ns * 8 + tap + (lane & 7);
                    int kk = pair * 32 + ((lane >> 3) & 3) * 8;
                    u32 a = bufbase + (u32)((row * WST + kk) * 2);
                    u32 b0, b1, b2, b3, l0, l1, l2, l3;
                    ldsm_x4(b0, b1, b2, b3, a);
                    ldsm_x4(l0, l1, l2, l3, a + (u32)(66 * WST * 2));
                    if (tap == 0 && m0[ns]) { b0 = b1 = b2 = b3 = l0 = l1 = l2 = l3 = 0u; }
                    if (tap == 2 && m2[ns]) { b0 = b1 = b2 = b3 = l0 = l1 = l2 = l3 = 0u; }
                    mma16816(d[ns][0], d[ns][1], d[ns][2], d[ns][3],
                             AH[tap][0].x, AH[tap][0].y, AH[tap][0].z, AH[tap][0].w, b0, b1);
                    mma16816(d[ns][0], d[ns][1], d[ns][2], d[ns][3],
                             AH[tap][0].x, AH[tap][0].y, AH[tap][0].z, AH[tap][0].w, l0, l1);
                    mma16816(d[ns][0], d[ns][1], d[ns][2], d[ns][3],
                             AL[tap][0].x, AL[tap][0].y, AL[tap][0].z, AL[tap][0].w, b0, b1);
                    mma16816(d[ns][0], d[ns][1], d[ns][2], d[ns][3],
                             AH[tap][1].x, AH[tap][1].y, AH[tap][1].z, AH[tap][1].w, b2, b3);
                    mma16816(d[ns][0], d[ns][1], d[ns][2], d[ns][3],
                             AH[tap][1].x, AH[tap][1].y, AH[tap][1].z, AH[tap][1].w, l2, l3);
                    mma16816(d[ns][0], d[ns][1], d[ns][2], d[ns][3],
                             AL[tap][1].x, AL[tap][1].y, AL[tap][1].z, AL[tap][1].w, b2, b3);
                }
            }
        }

#pragma unroll
        for (int ns = 0; ns < 8; ns++) {
            int col0 = base + ns * 8 + 2 * lc;
            float s2 = 1.f / (1.f + __expf(-(d[ns][2] + bQ)));
            float s3 = 1.f / (1.f + __expf(-(d[ns][3] + bQ)));
            float v0 = (d[ns][0] + bP) * s2;
            float v1 = (d[ns][1] + bP) * s3;
            if (OUTBF) {
                __nv_bfloat16 h0 = __float2bfloat16(v0);
                __nv_bfloat16 h1 = __float2bfloat16(v1);
                oh[(size_t)col0 * 64 + h] = h0;
                ol[(size_t)col0 * 64 + h] = __float2bfloat16(v0 - __bfloat162float(h0));
                oh[(size_t)(col0 + 1) * 64 + h] = h1;
                ol[(size_t)(col0 + 1) * 64 + h] = __float2bfloat16(v1 - __bfloat162float(h1));
            } else {
                outf[(size_t)col0 * 64 + h]       = v0;
                outf[(size_t)(col0 + 1) * 64 + h] = v1;
            }
        }
        __syncthreads();
        sel ^= 1;
    }
}

// ---------------- fused GCN (layout [n][t][c]), bf16 hi/lo output ----------------
__global__ void __launch_bounds__(192)
gcn_fused_kernel(const float* __restrict__ in,
                 __nv_bfloat16* __restrict__ oh, __nv_bfloat16* __restrict__ ol,
                 const float* __restrict__ W, const float* __restrict__ bias) {
    __shared__ __align__(16) float xs[768];
    __shared__ float Ws[64 * 65];
    int n = blockIdx.x, tid = threadIdx.x;

    for (int gi = tid; gi < 4096; gi += 192) {
        int o = gi >> 6, c = gi & 63;
        Ws[c * 65 + o] = W[gi];
    }

    float d = g_dis[n];
    float d2 = d * d;
    float4 acc = ((const float4*)(in + (size_t)n * FEAT))[tid];
    acc.x *= d2; acc.y *= d2; acc.z *= d2; acc.w *= d2;

    int e = g_rowptr[n], e1 = g_rowptr[n + 1];
    for (; e + 4 <= e1; e += 4) {
        ull p0 = g_edge[e], p1 = g_edge[e + 1], p2 = g_edge[e + 2], p3 = g_edge[e + 3];
        int s0 = (int)(unsigned)p0, s1 = (int)(unsigned)p1;
        int s2 = (int)(unsigned)p2, s3 = (int)(unsigned)p3;
        float c0 = __uint_as_float((unsigned)(p0 >> 32));
        float c1 = __uint_as_float((unsigned)(p1 >> 32));
        float c2 = __uint_as_float((unsigned)(p2 >> 32));
        float c3 = __uint_as_float((unsigned)(p3 >> 32));
        float4 v0 = ((const float4*)(in + (size_t)s0 * FEAT))[tid];
        float4 v1 = ((const float4*)(in + (size_t)s1 * FEAT))[tid];
        float4 v2 = ((const float4*)(in + (size_t)s2 * FEAT))[tid];
        float4 v3 = ((const float4*)(in + (size_t)s3 * FEAT))[tid];
        acc.x += c0 * v0.x + c1 * v1.x + c2 * v2.x + c3 * v3.x;
        acc.y += c0 * v0.y + c1 * v1.y + c2 * v2.y + c3 * v3.y;
        acc.z += c0 * v0.z + c1 * v1.z + c2 * v2.z + c3 * v3.z;
        acc.w += c0 * v0.w + c1 * v1.w + c2 * v2.w + c3 * v3.w;
    }
    for (; e < e1; e++) {
        ull p = g_edge[e];
        int s = (int)(unsigned)p;
        float cf = __uint_as_float((unsigned)(p >> 32));
        float4 v = ((const float4*)(in + (size_t)s * FEAT))[tid];
        acc.x += cf * v.x; acc.y += cf * v.y; acc.z += cf * v.z; acc.w += cf * v.w;
    }
    ((float4*)xs)[tid] = acc;
    __syncthreads();

    int o = tid & 63, tg = tid >> 6;
    float a0 = 0.f, a1 = 0.f, a2 = 0.f, a3 = 0.f;
#pragma unroll 8
    for (int c = 0; c < 64; c++) {
        float wv = Ws[c * 65 + o];
        const float* xp = xs + c;
        a0 += wv * xp[(tg * 4 + 0) * 64];
        a1 += wv * xp[(tg * 4 + 1) * 64];
        a2 += wv * xp[(tg * 4 + 2) * 64];
        a3 += wv * xp[(tg * 4 + 3) * 64];
    }
    float bv = bias[o];
    float rr[4] = {fmaxf(a0 + bv, 0.f), fmaxf(a1 + bv, 0.f),
                   fmaxf(a2 + bv, 0.f), fmaxf(a3 + bv, 0.f)};
#pragma unroll
    for (int i = 0; i < 4; i++) {
        size_t idx = (size_t)n * FEAT + (size_t)(tg * 4 + i) * 64 + o;
        __nv_bfloat16 hv = __float2bfloat16(rr[i]);
        oh[idx] = hv;
        ol[idx] = __float2bfloat16(rr[i] - __bfloat162float(hv));
    }
}

// ---------------- final conv (layout [n][t][c]) ----------------
__global__ void fin_kernel(const float* __restrict__ in, const float* __restrict__ w,
                           const float* __restrict__ b, float* __restrict__ out) {
    extern __shared__ float smf[];
    float* wt = smf;              // 12 rows, stride 772, reindexed [t*64+h]
    float* xt = smf + 12 * 772;   // 16 nodes, stride 772
    int tid = threadIdx.x;        // 192
    for (int i = tid; i < 12 * 768; i += 192) {
        int o = i / 768, r = i - o * 768;
        int t = r >> 6, hh = r & 63;
        wt[o * 772 + r] = w[o * 768 + hh * 12 + t];
    }
    int n0 = blockIdx.x * 16;
    for (int gi = tid; gi < 16 * 192; gi += 192) {
        int node = gi / 192, j = gi - node * 192;
        ((float4*)(xt + node * 772))[j] =
            ((const float4*)(in + (size_t)(n0 + node) * FEAT))[j];
    }
    __syncthreads();
    int node = tid / 12, o = tid - node * 12;
    const float* wr = wt + o * 772;
    const float* xr = xt + node * 772;
    float acc = 0.f;
#pragma unroll 4
    for (int j = 0; j < 192; j++) {
        float4 a = ((const float4*)wr)[j];
        float4 v = ((const float4*)xr)[j];
        acc += a.x * v.x + a.y * v.y + a.z * v.z + a.w * v.w;
    }
    out[(size_t)(n0 + node) * 12 + o] = acc + b[o];
}

// ---------------- launch ----------------
extern "C" void kernel_launch(void* const* d_in, const int* in_sizes, int n_in,
                              void* d_out, int out_size) {
    const float* x      = (const float*)d_in[0];
    const int*   ei     = (const int*)d_in[1];
    const float* ew     = (const float*)d_in[2];
    const float* tc1a_w = (const float*)d_in[3];
    const float* tc1a_b = (const float*)d_in[4];
    const float* gc1_w  = (const float*)d_in[5];
    const float* gc1_b  = (const float*)d_in[6];
    const float* tc1b_w = (const float*)d_in[7];
    const float* tc1b_b = (const float*)d_in[8];
    const float* tc2a_w = (const float*)d_in[9];
    const float* tc2a_b = (const float*)d_in[10];
    const float* gc2_w  = (const float*)d_in[11];
    const float* gc2_b  = (const float*)d_in[12];
    const float* tc2b_w = (const float*)d_in[13];
    const float* tc2b_b = (const float*)d_in[14];
    const float* fin_w  = (const float*)d_in[15];
    const float* fin_b  = (const float*)d_in[16];
    float* out = (float*)d_out;

    float *pA, *pB; uint4* pW;
    __nv_bfloat16 *pH1, *pL1, *pH2, *pL2;
    cudaGetSymbolAddress((void**)&pA, g_bufA);
    cudaGetSymbolAddress((void**)&pB, g_bufB);
    cudaGetSymbolAddress((void**)&pW, g_wfrag);
    cudaGetSymbolAddress((void**)&pH1, g_h1);
    cudaGetSymbolAddress((void**)&pL1, g_l1);
    cudaGetSymbolAddress((void**)&pH2, g_h2);
    cudaGetSymbolAddress((void**)&pL2, g_l2);

    const int smem32 = 2 * 132 * 40 * 2;    // 21120
    const int smem64 = 2 * 132 * 72 * 2;    // 38016
    const int smemF  = (12 + 16) * 772 * 4;
    cudaFuncSetAttribute(fin_kernel, cudaFuncAttributeMaxDynamicSharedMemorySize, smemF);
    cudaFuncSetAttribute((const void*)tconv_mma_kernel<64, true>,
                         cudaFuncAttributeMaxDynamicSharedMemorySize, smem64);
    cudaFuncSetAttribute((const void*)tconv_mma_kernel<64, false>,
                         cudaFuncAttributeMaxDynamicSharedMemorySize, smem64);
    cudaFuncSetAttribute((const void*)tconv_mma_kernel<32, false>,
                         cudaFuncAttributeMaxDynamicSharedMemorySize, smem32);

    // ---- fork/join: CSR chain on a side stream, overlapped with prep+tc1a ----
    cudaStream_t s1;
    cudaStreamCreateWithFlags(&s1, cudaStreamNonBlocking);
    cudaEvent_t evFork, evJoin;
    cudaEventCreateWithFlags(&evFork, cudaEventDisableTiming);
    cudaEventCreateWithFlags(&evJoin, cudaEventDisableTiming);

    cudaEventRecord(evFork, 0);
    cudaStreamWaitEvent(s1, evFork, 0);

    // launch #1 (side stream): CSR zero
    zero_kernel<<<(NN + 255) / 256, 256, 0, s1>>>();
    // launches #2,#3 (main): prep + transpose
    prep_w_kernel<<<(21504 + 255) / 256, 256>>>(tc1a_w, tc1b_w, tc2a_w, tc2b_w);
    transpose_x_kernel<<<(NN * 384 + 255) / 256, 256>>>(x, pH1, pL1);
    // launch #4 (main): tc1a — ncu capture slot
    tconv_mma_kernel<32, false><<<296, 256, smem32>>>(pH1, pL1, pW, tc1a_b, pA, 0, 0);
    // side stream: rest of CSR build
    hist_kernel<<<(EE + 255) / 256, 256, 0, s1>>>(ei, ew);
    scan_kernel<<<1, 1024, 0, s1>>>();
    scatter_kernel<<<(EE + 255) / 256, 256, 0, s1>>>(ei, ew);
    cudaEventRecord(evJoin, s1);
    // join before gcn1
    cudaStreamWaitEvent(0, evJoin, 0);

    // gcn1: A -> (H1,L1)
    gcn_fused_kernel<<<NN, 192>>>(pA, pH1, pL1, gc1_w, gc1_b);
    // tc1b: (H1,L1) -> (H2,L2)
    tconv_mma_kernel<64, true><<<296, 256, smem64>>>(pH1, pL1, pW + 3072, tc1b_b, 0, pH2, pL2);
    // tc2a: (H2,L2) -> A fp32
    tconv_mma_kernel<64, false><<<296, 256, smem64>>>(pH2, pL2, pW + 9216, tc2a_b, pA, 0, 0);
    // gcn2: A -> (H1,L1)
    gcn_fused_kernel<<<NN, 192>>>(pA, pH1, pL1, gc2_w, gc2_b);
    // tc2b: (H1,L1) -> B fp32
    tconv_mma_kernel<64, false><<<296, 256, smem64>>>(pH1, pL1, pW + 15360, tc2b_b, pB, 0, 0);
    // fin: B -> out
    fin_kernel<<<NN / 16, 192, smemF>>>(pB, fin_w, fin_b, out);
}

// round 13
// speedup vs baseline: 1.1359x; 1.0552x over previous
#include <cuda_runtime.h>
#include <cuda_bf16.h>
#include <math.h>

#define NN    10000
#define EE    160000
#define FEAT  768           // 64*12
#define TOTC  120000        // NN*12 gemm columns
typedef unsigned long long ull;
typedef unsigned u32;

// ---------------- scratch (device globals; no allocation) ----------------
__device__ float g_bufA[NN * FEAT];
__device__ float g_bufB[NN * FEAT];
__device__ __nv_bfloat16 g_h1[NN * FEAT];
__device__ __nv_bfloat16 g_l1[NN * FEAT];
__device__ __nv_bfloat16 g_h2[NN * FEAT];
__device__ __nv_bfloat16 g_l2[NN * FEAT];
__device__ float g_deg[NN];
__device__ float g_dis[NN];
__device__ int   g_cnt[NN];
__device__ int   g_rowptr[NN + 1];
__device__ ull   g_edge[EE];
__device__ u32   g_wfrag[86016];   // frag-ordered hi/lo tconv weights, 4 layers
__device__ float g_wt[8192];       // transposed GCN weights [c][o], 2 layers

// ---------------- helpers ----------------
__device__ __forceinline__ u32 smem_u32(const void* p) {
    u32 a;
    asm("{ .reg .u64 t; cvta.to.shared.u64 t, %1; cvt.u32.u64 %0, t; }" : "=r"(a) : "l"(p));
    return a;
}
__device__ __forceinline__ u32 pack_bf2(float a, float b) {   // low half = a, high = b
    u32 r;
    asm("cvt.rn.satfinite.bf16x2.f32 %0, %1, %2;" : "=r"(r) : "f"(b), "f"(a));
    return r;
}
__device__ __forceinline__ void ldsm_x4(u32& r0, u32& r1, u32& r2, u32& r3, u32 a) {
    asm volatile("ldmatrix.sync.aligned.m8n8.x4.shared.b16 {%0,%1,%2,%3}, [%4];"
                 : "=r"(r0), "=r"(r1), "=r"(r2), "=r"(r3) : "r"(a));
}
__device__ __forceinline__ void mma16816(float& d0, float& d1, float& d2, float& d3,
                                         u32 a0, u32 a1, u32 a2, u32 a3, u32 b0, u32 b1) {
    asm volatile("mma.sync.aligned.m16n8k16.row.col.f32.bf16.bf16.f32 "
                 "{%0,%1,%2,%3}, {%4,%5,%6,%7}, {%8,%9}, {%0,%1,%2,%3};"
                 : "+f"(d0), "+f"(d1), "+f"(d2), "+f"(d3)
                 : "r"(a0), "r"(a1), "r"(a2), "r"(a3), "r"(b0), "r"(b1));
}
__device__ __forceinline__ void cp_async16(u32 dst, const void* src, bool v) {
    asm volatile("cp.async.cg.shared.global [%0], [%1], 16, %2;"
                 :: "r"(dst), "l"(src), "r"(v ? 16 : 0));
}
#define CP_COMMIT() asm volatile("cp.async.commit_group;" ::: "memory")
#define CP_WAIT1()  asm volatile("cp.async.wait_group 1;" ::: "memory")
#define CP_WAIT0()  asm volatile("cp.async.wait_group 0;" ::: "memory")

// ---------------- CSR build ----------------
__global__ void zero_kernel() {
    int i = blockIdx.x * blockDim.x + threadIdx.x;
    if (i < NN) { g_deg[i] = 0.f; g_cnt[i] = 0; }
}
__global__ void hist_kernel(const int* __restrict__ ei, const float* __restrict__ ew) {
    int e = blockIdx.x * blockDim.x + threadIdx.x;
    if (e < EE) {
        int d = ei[EE + e];
        atomicAdd(&g_deg[d], ew[e]);
        atomicAdd(&g_cnt[d], 1);
    }
}
// single block, warp-shuffle scan
__global__ void scan_kernel() {
    __shared__ int wsum[32];
    __shared__ int choff;
    int tid = threadIdx.x;
    int lane = tid & 31, w = tid >> 5;
    if (tid == 0) choff = 0;
    __syncthreads();
    for (int base = 0; base < NN; base += 1024) {
        int i = base + tid;
        int v = (i < NN) ? g_cnt[i] : 0;
        if (i < NN) { g_dis[i] = rsqrtf(g_deg[i] + 1.0f); g_cnt[i] = 0; }
        int s = v;
#pragma unroll
        for (int d = 1; d < 32; d <<= 1) {
            int t = __shfl_up_sync(~0u, s, d);
            if (lane >= d) s += t;
        }
        if (lane == 31) wsum[w] = s;
        __syncthreads();
        if (w == 0) {
            int ws = wsum[lane];
#pragma unroll
            for (int d = 1; d < 32; d <<= 1) {
                int t = __shfl_up_sync(~0u, ws, d);
                if (lane >= d) ws += t;
            }
            wsum[lane] = ws;
        }
        __syncthreads();
        int off = choff + ((w > 0) ? wsum[w - 1] : 0);
        int total = wsum[31];
        if (i < NN) g_rowptr[i] = off + s - v;
        __syncthreads();
        if (tid == 0) choff += total;
        __syncthreads();
    }
    if (tid == 0) g_rowptr[NN] = choff;
}
__global__ void scatter_kernel(const int* __restrict__ ei, const float* __restrict__ ew) {
    int e = blockIdx.x * blockDim.x + threadIdx.x;
    if (e < EE) {
        int d = ei[EE + e];
        int s = ei[e];
        int pos = g_rowptr[d] + atomicAdd(&g_cnt[d], 1);
        float coef = g_dis[s] * ew[e] * g_dis[d];
        g_edge[pos] = ((ull)__float_as_uint(coef) << 32) | (unsigned)s;
    }
}

// ---------------- weight prepack: tconv frag order + gcn transpose ----------
__global__ void prep_w_kernel(const float* __restrict__ w0, const float* __restrict__ w1,
                              const float* __restrict__ w2, const float* __restrict__ w3,
                              const float* __restrict__ g1, const float* __restrict__ g2) {
    int v = blockIdx.x * 256 + threadIdx.x;
    if (v >= 29696) return;
    if (v >= 21504) {                       // GCN W transpose: wt[c*64+o] = W[o*64+c]
        int r = v - 21504;
        const float* g = (r < 4096) ? g1 : g2;
        int i = r & 4095;
        int c = i >> 6, o = i & 63;
        g_wt[r] = g[o * 64 + c];
        return;
    }
    const float* w; int C, off;
    if (v < 3072)       { w = w0; C = 32; off = 0; }
    else if (v < 9216)  { w = w1; C = 64; off = 3072; }
    else if (v < 15360) { w = w2; C = 64; off = 9216; }
    else                { w = w3; C = 64; off = 15360; }
    int r = v - off;
    int KS = C / 16;
    int lane = r & 31; r >>= 5;
    int wid = r & 7;  r >>= 3;
    int ks = r % KS;  r /= KS;
    int tap = r % 3;  r /= 3;
    int s = r;
    u32 o4[4];
#pragma unroll
    for (int rr = 0; rr < 4; rr++) {
        float vv[2];
#pragma unroll
        for (int b = 0; b < 2; b++) {
            int m_local = (rr & 1) * 8 + (lane >> 2);
            int k = (rr >> 1) * 8 + (lane & 3) * 2 + b;
            int hh = wid * 8 + (m_local & 7);
            int orig = (m_local < 8) ? hh : 64 + hh;
            int c = ks * 16 + k;
            float val = w[(size_t)orig * C * 3 + c * 3 + tap];
            float hi = __bfloat162float(__float2bfloat16(val));
            vv[b] = (s == 0) ? hi : (val - hi);
        }
        o4[rr] = pack_bf2(vv[0], vv[1]);
    }
    ((uint4*)g_wfrag)[v] = make_uint4(o4[0], o4[1], o4[2], o4[3]);
}

// ---------------- input transpose + split: [n][32][12] -> hi/lo [n][12][32] ----
__global__ void transpose_x_kernel(const float* __restrict__ in,
                                   __nv_bfloat16* __restrict__ oh,
                                   __nv_bfloat16* __restrict__ ol) {
    int i = blockIdx.x * 256 + threadIdx.x;
    if (i < NN * 384) {
        int c = i & 31;
        int t = (i >> 5) % 12;
        int n = i / 384;
        float v = in[n * 384 + c * 12 + t];
        __nv_bfloat16 h = __float2bfloat16(v);
        oh[i] = h;
        ol[i] = __float2bfloat16(v - __bfloat162float(h));
    }
}

// ---------------- tensor-core gated temporal conv, cp.async double-buffered ----
template <int C, bool OUTBF>
__global__ void __launch_bounds__(256, 2)
tconv_mma_kernel(const __nv_bfloat16* __restrict__ xh, const __nv_bfloat16* __restrict__ xl,
                 const uint4* __restrict__ wf, const float* __restrict__ bias,
                 float* __restrict__ outf,
                 __nv_bfloat16* __restrict__ oh, __nv_bfloat16* __restrict__ ol) {
    const int KS = C / 16;
    const int PAIRS = KS / 2;
    const int WST = C + 8;                 // smem row stride (bf16)
    const int BUFSZ = 132 * WST;           // one buffer, bf16 elems
    const int CHK = C / 8;                 // 16B chunks per row
    const int NCH = 66 * CHK;
    extern __shared__ __align__(16) __nv_bfloat16 sw[];
    const int tid = threadIdx.x;
    const int lane = tid & 31, wid = tid >> 5;
    u32 sb = smem_u32(sw);

    float bP = bias[wid * 8 + (lane >> 2)];
    float bQ = bias[64 + wid * 8 + (lane >> 2)];
    const int h = wid * 8 + (lane >> 2);
    const int lc = lane & 3;
    const int lq = lane >> 2;
    const int NT = TOTC / 64;

    auto stage = [&](int t, int bufsel) {
        int base = t * 64;
        for (int i = tid; i < 2 * NCH; i += 256) {
            int img = (i >= NCH);
            int j = i - img * NCH;
            int row = j / CHK, ch = j - row * CHK;
            int col = base - 1 + row;
            bool valid = (col >= 0 && col < TOTC);
            size_t cc = valid ? (size_t)col : 0;
            const __nv_bfloat16* src = (img ? xl : xh) + cc * C + ch * 8;
            u32 dst = sb + (u32)((bufsel * BUFSZ + (img * 66 + row) * WST) * 2 + ch * 16);
            cp_async16(dst, src, valid);
        }
    };

    int t0 = blockIdx.x;
    if (t0 < NT) stage(t0, 0);
    CP_COMMIT();
    int sel = 0;

    for (int tile = t0; tile < NT; tile += gridDim.x) {
        int base = tile * 64;
        int nxt = tile + gridDim.x;
        if (nxt < NT) {
            stage(nxt, sel ^ 1);
            CP_COMMIT();
            CP_WAIT1();
        } else {
            CP_WAIT0();
        }
        __syncthreads();

        int m0[8], m2[8];
#pragma unroll
        for (int ns = 0; ns < 8; ns++) {
            int tm = (base + ns * 8 + lq) % 12;
            m0[ns] = (tm == 0);
            m2[ns] = (tm == 11);
        }

        float d[8][4];
#pragma unroll
        for (int ns = 0; ns < 8; ns++) { d[ns][0] = d[ns][1] = d[ns][2] = d[ns][3] = 0.f; }

        u32 bufbase = sb + (u32)(sel * BUFSZ * 2);

#pragma unroll
        for (int pair = 0; pair < PAIRS; pair++) {
            uint4 AH[3][2], AL[3][2];
#pragma unroll
            for (int tap = 0; tap < 3; tap++)
#pragma unroll
                for (int k2 = 0; k2 < 2; k2++) {
                    AH[tap][k2] = wf[((tap * KS + pair * 2 + k2) * 8 + wid) * 32 + lane];
                    AL[tap][k2] = wf[(((3 + tap) * KS + pair * 2 + k2) * 8 + wid) * 32 + lane];
                }
#pragma unroll
            for (int ns = 0; ns < 8; ns++) {
#pragma unroll
                for (int tap = 0; tap < 3; tap++) {
                    int row = ns * 8 + tap + (lane & 7);
                    int kk = pair * 32 + ((lane >> 3) & 3) * 8;
                    u32 a = bufbase + (u32)((row * WST + kk) * 2);
                    u32 b0, b1, b2, b3, l0, l1, l2, l3;
                    ldsm_x4(b0, b1, b2, b3, a);
                    ldsm_x4(l0, l1, l2, l3, a + (u32)(66 * WST * 2));
                    if (tap == 0 && m0[ns]) { b0 = b1 = b2 = b3 = l0 = l1 = l2 = l3 = 0u; }
                    if (tap == 2 && m2[ns]) { b0 = b1 = b2 = b3 = l0 = l1 = l2 = l3 = 0u; }
                    mma16816(d[ns][0], d[ns][1], d[ns][2], d[ns][3],
                             AH[tap][0].x, AH[tap][0].y, AH[tap][0].z, AH[tap][0].w, b0, b1);
                    mma16816(d[ns][0], d[ns][1], d[ns][2], d[ns][3],
                             AH[tap][0].x, AH[tap][0].y, AH[tap][0].z, AH[tap][0].w, l0, l1);
                    mma16816(d[ns][0], d[ns][1], d[ns][2], d[ns][3],
                             AL[tap][0].x, AL[tap][0].y, AL[tap][0].z, AL[tap][0].w, b0, b1);
                    mma16816(d[ns][0], d[ns][1], d[ns][2], d[ns][3],
                             AH[tap][1].x, AH[tap][1].y, AH[tap][1].z, AH[tap][1].w, b2, b3);
                    mma16816(d[ns][0], d[ns][1], d[ns][2], d[ns][3],
                             AH[tap][1].x, AH[tap][1].y, AH[tap][1].z, AH[tap][1].w, l2, l3);
                    mma16816(d[ns][0], d[ns][1], d[ns][2], d[ns][3],
                             AL[tap][1].x, AL[tap][1].y, AL[tap][1].z, AL[tap][1].w, b2, b3);
                }
            }
        }

#pragma unroll
        for (int ns = 0; ns < 8; ns++) {
            int col0 = base + ns * 8 + 2 * lc;
            float s2 = 1.f / (1.f + __expf(-(d[ns][2] + bQ)));
            float s3 = 1.f / (1.f + __expf(-(d[ns][3] + bQ)));
            float v0 = (d[ns][0] + bP) * s2;
            float v1 = (d[ns][1] + bP) * s3;
            if (OUTBF) {
                __nv_bfloat16 h0 = __float2bfloat16(v0);
                __nv_bfloat16 h1 = __float2bfloat16(v1);
                oh[(size_t)col0 * 64 + h] = h0;
                ol[(size_t)col0 * 64 + h] = __float2bfloat16(v0 - __bfloat162float(h0));
                oh[(size_t)(col0 + 1) * 64 + h] = h1;
                ol[(size_t)(col0 + 1) * 64 + h] = __float2bfloat16(v1 - __bfloat162float(h1));
            } else {
                outf[(size_t)col0 * 64 + h]       = v0;
                outf[(size_t)(col0 + 1) * 64 + h] = v1;
            }
        }
        __syncthreads();
        sel ^= 1;
    }
}

// ---------------- fused GCN: gather + transform via L1-resident transposed W ----
__global__ void __launch_bounds__(192)
gcn_fused_kernel(const float* __restrict__ in,
                 __nv_bfloat16* __restrict__ oh, __nv_bfloat16* __restrict__ ol,
                 const float* __restrict__ Wt, const float* __restrict__ bias) {
    __shared__ __align__(16) float xs[768];
    int n = blockIdx.x, tid = threadIdx.x;

    float d = g_dis[n];
    float d2 = d * d;
    float4 acc = ((const float4*)(in + (size_t)n * FEAT))[tid];
    acc.x *= d2; acc.y *= d2; acc.z *= d2; acc.w *= d2;

    int e = g_rowptr[n], e1 = g_rowptr[n + 1];
    for (; e + 8 <= e1; e += 8) {
        ull p[8]; float4 v[8];
#pragma unroll
        for (int j = 0; j < 8; j++) p[j] = g_edge[e + j];
#pragma unroll
        for (int j = 0; j < 8; j++)
            v[j] = ((const float4*)(in + (size_t)(int)(unsigned)p[j] * FEAT))[tid];
#pragma unroll
        for (int j = 0; j < 8; j++) {
            float cf = __uint_as_float((unsigned)(p[j] >> 32));
            acc.x += cf * v[j].x; acc.y += cf * v[j].y;
            acc.z += cf * v[j].z; acc.w += cf * v[j].w;
        }
    }
    for (; e + 2 <= e1; e += 2) {
        ull p0 = g_edge[e], p1 = g_edge[e + 1];
        float4 v0 = ((const float4*)(in + (size_t)(int)(unsigned)p0 * FEAT))[tid];
        float4 v1 = ((const float4*)(in + (size_t)(int)(unsigned)p1 * FEAT))[tid];
        float c0 = __uint_as_float((unsigned)(p0 >> 32));
        float c1 = __uint_as_float((unsigned)(p1 >> 32));
        acc.x += c0 * v0.x + c1 * v1.x;
        acc.y += c0 * v0.y + c1 * v1.y;
        acc.z += c0 * v0.z + c1 * v1.z;
        acc.w += c0 * v0.w + c1 * v1.w;
    }
    if (e < e1) {
        ull p = g_edge[e];
        float cf = __uint_as_float((unsigned)(p >> 32));
        float4 v = ((const float4*)(in + (size_t)(int)(unsigned)p * FEAT))[tid];
        acc.x += cf * v.x; acc.y += cf * v.y; acc.z += cf * v.z; acc.w += cf * v.w;
    }
    ((float4*)xs)[tid] = acc;
    __syncthreads();

    // out[t][o] = relu(sum_c Wt[c*64+o] * xs[t*64+c] + b[o]); Wt L1-resident
    int o = tid & 63, tg = tid >> 6;
    float a0 = 0.f, a1 = 0.f, a2 = 0.f, a3 = 0.f;
    const float* xp = xs + tg * 256;   // 4 t rows of 64
#pragma unroll 8
    for (int c = 0; c < 64; c++) {
        float wv = __ldg(Wt + c * 64 + o);
        a0 += wv * xp[c];
        a1 += wv * xp[64 + c];
        a2 += wv * xp[128 + c];
        a3 += wv * xp[192 + c];
    }
    float bv = bias[o];
    float rr[4] = {fmaxf(a0 + bv, 0.f), fmaxf(a1 + bv, 0.f),
                   fmaxf(a2 + bv, 0.f), fmaxf(a3 + bv, 0.f)};
#pragma unroll
    for (int i = 0; i < 4; i++) {
        size_t idx = (size_t)n * FEAT + (size_t)(tg * 4 + i) * 64 + o;
        __nv_bfloat16 hv = __float2bfloat16(rr[i]);
        oh[idx] = hv;
        ol[idx] = __float2bfloat16(rr[i] - __bfloat162float(hv));
    }
}

// ---------------- final conv (layout [n][t][c]) ----------------
__global__ void fin_kernel(const float* __restrict__ in, const float* __restrict__ w,
                           const float* __restrict__ b, float* __restrict__ out) {
    extern __shared__ float smf[];
    float* wt = smf;              // 12 rows, stride 772, reindexed [t*64+h]
    float* xt = smf + 12 * 772;   // 16 nodes, stride 772
    int tid = threadIdx.x;        // 192
    for (int i = tid; i < 12 * 768; i += 192) {
        int o = i / 768, r = i - o * 768;
        int t = r >> 6, hh = r & 63;
        wt[o * 772 + r] = w[o * 768 + hh * 12 + t];
    }
    int n0 = blockIdx.x * 16;
    for (int gi = tid; gi < 16 * 192; gi += 192) {
        int node = gi / 192, j = gi - node * 192;
        ((float4*)(xt + node * 772))[j] =
            ((const float4*)(in + (size_t)(n0 + node) * FEAT))[j];
    }
    __syncthreads();
    int node = tid / 12, o = tid - node * 12;
    const float* wr = wt + o * 772;
    const float* xr = xt + node * 772;
    float acc = 0.f;
#pragma unroll 4
    for (int j = 0; j < 192; j++) {
        float4 a = ((const float4*)wr)[j];
        float4 v = ((const float4*)xr)[j];
        acc += a.x * v.x + a.y * v.y + a.z * v.z + a.w * v.w;
    }
    out[(size_t)(n0 + node) * 12 + o] = acc + b[o];
}

// ---------------- launch ----------------
extern "C" void kernel_launch(void* const* d_in, const int* in_sizes, int n_in,
                              void* d_out, int out_size) {
    const float* x      = (const float*)d_in[0];
    const int*   ei     = (const int*)d_in[1];
    const float* ew     = (const float*)d_in[2];
    const float* tc1a_w = (const float*)d_in[3];
    const float* tc1a_b = (const float*)d_in[4];
    const float* gc1_w  = (const float*)d_in[5];
    const float* gc1_b  = (const float*)d_in[6];
    const float* tc1b_w = (const float*)d_in[7];
    const float* tc1b_b = (const float*)d_in[8];
    const float* tc2a_w = (const float*)d_in[9];
    const float* tc2a_b = (const float*)d_in[10];
    const float* gc2_w  = (const float*)d_in[11];
    const float* gc2_b  = (const float*)d_in[12];
    const float* tc2b_w = (const float*)d_in[13];
    const float* tc2b_b = (const float*)d_in[14];
    const float* fin_w  = (const float*)d_in[15];
    const float* fin_b  = (const float*)d_in[16];
    float* out = (float*)d_out;

    float *pA, *pB, *pWT; uint4* pW;
    __nv_bfloat16 *pH1, *pL1, *pH2, *pL2;
    cudaGetSymbolAddress((void**)&pA, g_bufA);
    cudaGetSymbolAddress((void**)&pB, g_bufB);
    cudaGetSymbolAddress((void**)&pW, g_wfrag);
    cudaGetSymbolAddress((void**)&pWT, g_wt);
    cudaGetSymbolAddress((void**)&pH1, g_h1);
    cudaGetSymbolAddress((void**)&pL1, g_l1);
    cudaGetSymbolAddress((void**)&pH2, g_h2);
    cudaGetSymbolAddress((void**)&pL2, g_l2);

    const int smem32 = 2 * 132 * 40 * 2;    // 21120
    const int smem64 = 2 * 132 * 72 * 2;    // 38016
    const int smemF  = (12 + 16) * 772 * 4;
    cudaFuncSetAttribute(fin_kernel, cudaFuncAttributeMaxDynamicSharedMemorySize, smemF);
    cudaFuncSetAttribute((const void*)tconv_mma_kernel<64, true>,
                         cudaFuncAttributeMaxDynamicSharedMemorySize, smem64);
    cudaFuncSetAttribute((const void*)tconv_mma_kernel<64, false>,
                         cudaFuncAttributeMaxDynamicSharedMemorySize, smem64);
    cudaFuncSetAttribute((const void*)tconv_mma_kernel<32, false>,
                         cudaFuncAttributeMaxDynamicSharedMemorySize, smem32);

    // ---- fork/join: CSR chain on a side stream, overlapped with prep+tc1a ----
    cudaStream_t s1;
    cudaStreamCreateWithFlags(&s1, cudaStreamNonBlocking);
    cudaEvent_t evFork, evJoin;
    cudaEventCreateWithFlags(&evFork, cudaEventDisableTiming);
    cudaEventCreateWithFlags(&evJoin, cudaEventDisableTiming);

    cudaEventRecord(evFork, 0);
    cudaStreamWaitEvent(s1, evFork, 0);

    zero_kernel<<<(NN + 255) / 256, 256, 0, s1>>>();
    prep_w_kernel<<<(29696 + 255) / 256, 256>>>(tc1a_w, tc1b_w, tc2a_w, tc2b_w, gc1_w, gc2_w);
    transpose_x_kernel<<<(NN * 384 + 255) / 256, 256>>>(x, pH1, pL1);
    // tc1a — ncu capture slot
    tconv_mma_kernel<32, false><<<296, 256, smem32>>>(pH1, pL1, pW, tc1a_b, pA, 0, 0);
    hist_kernel<<<(EE + 255) / 256, 256, 0, s1>>>(ei, ew);
    scan_kernel<<<1, 1024, 0, s1>>>();
    scatter_kernel<<<(EE + 255) / 256, 256, 0, s1>>>(ei, ew);
    cudaEventRecord(evJoin, s1);
    cudaStreamWaitEvent(0, evJoin, 0);

    // gcn1: A -> (H1,L1)
    gcn_fused_kernel<<<NN, 192>>>(pA, pH1, pL1, pWT, gc1_b);
    // tc1b: (H1,L1) -> (H2,L2)
    tconv_mma_kernel<64, true><<<296, 256, smem64>>>(pH1, pL1, pW + 3072, tc1b_b, 0, pH2, pL2);
    // tc2a: (H2,L2) -> A fp32
    tconv_mma_kernel<64, false><<<296, 256, smem64>>>(pH2, pL2, pW + 9216, tc2a_b, pA, 0, 0);
    // gcn2: A -> (H1,L1)
    gcn_fused_kernel<<<NN, 192>>>(pA, pH1, pL1, pWT + 4096, gc2_b);
    // tc2b: (H1,L1) -> B fp32
    tconv_mma_kernel<64, false><<<296, 256, smem64>>>(pH1, pL1, pW + 15360, tc2b_b, pB, 0, 0);
    // fin: B -> out
    fin_kernel<<<NN / 16, 192, smemF>>>(pB, fin_w, fin_b, out);
}

// round 15
// speedup vs baseline: 1.3676x; 1.2040x over previous
#include <cuda_runtime.h>
#include <cuda_fp16.h>
#include <math.h>

#define NN    10000
#define EE    160000
#define FEAT  768           // 64*12
#define TOTC  120000        // NN*12 gemm columns
typedef unsigned long long ull;
typedef unsigned u32;

// ---------------- scratch (device globals; no allocation) ----------------
__device__ float g_bufA[NN * FEAT];
__device__ float g_bufB[NN * FEAT];
__device__ __half g_h1[NN * FEAT];     // single fp16 activation images
__device__ __half g_h2[NN * FEAT];
__device__ float g_deg[NN];
__device__ float g_dis[NN];
__device__ int   g_cnt[NN];
__device__ int   g_rowptr[NN + 1];
__device__ ull   g_edge[EE];
__device__ u32   g_wfrag[86016];   // frag-ordered hi/lo fp16 tconv weights, 4 layers
__device__ float g_wt[8192];       // transposed GCN weights [c][o], 2 layers

// ---------------- helpers ----------------
__device__ __forceinline__ u32 smem_u32(const void* p) {
    u32 a;
    asm("{ .reg .u64 t; cvta.to.shared.u64 t, %1; cvt.u32.u64 %0, t; }" : "=r"(a) : "l"(p));
    return a;
}
__device__ __forceinline__ void ldsm_x4(u32& r0, u32& r1, u32& r2, u32& r3, u32 a) {
    asm volatile("ldmatrix.sync.aligned.m8n8.x4.shared.b16 {%0,%1,%2,%3}, [%4];"
                 : "=r"(r0), "=r"(r1), "=r"(r2), "=r"(r3) : "r"(a));
}
__device__ __forceinline__ void mma16816(float& d0, float& d1, float& d2, float& d3,
                                         u32 a0, u32 a1, u32 a2, u32 a3, u32 b0, u32 b1) {
    asm volatile("mma.sync.aligned.m16n8k16.row.col.f32.f16.f16.f32 "
                 "{%0,%1,%2,%3}, {%4,%5,%6,%7}, {%8,%9}, {%0,%1,%2,%3};"
                 : "+f"(d0), "+f"(d1), "+f"(d2), "+f"(d3)
                 : "r"(a0), "r"(a1), "r"(a2), "r"(a3), "r"(b0), "r"(b1));
}
__device__ __forceinline__ void cp_async16(u32 dst, const void* src, bool v) {
    asm volatile("cp.async.cg.shared.global [%0], [%1], 16, %2;"
                 :: "r"(dst), "l"(src), "r"(v ? 16 : 0));
}
#define CP_COMMIT() asm volatile("cp.async.commit_group;" ::: "memory")
#define CP_WAIT1()  asm volatile("cp.async.wait_group 1;" ::: "memory")
#define CP_WAIT0()  asm volatile("cp.async.wait_group 0;" ::: "memory")

// ---------------- CSR build ----------------
__global__ void zero_kernel() {
    int i = blockIdx.x * blockDim.x + threadIdx.x;
    if (i < NN) { g_deg[i] = 0.f; g_cnt[i] = 0; }
}
__global__ void hist_kernel(const int* __restrict__ ei, const float* __restrict__ ew) {
    int e = blockIdx.x * blockDim.x + threadIdx.x;
    if (e < EE) {
        int d = ei[EE + e];
        atomicAdd(&g_deg[d], ew[e]);
        atomicAdd(&g_cnt[d], 1);
    }
}
__global__ void scan_kernel() {
    __shared__ int wsum[32];
    __shared__ int choff;
    int tid = threadIdx.x;
    int lane = tid & 31, w = tid >> 5;
    if (tid == 0) choff = 0;
    __syncthreads();
    for (int base = 0; base < NN; base += 1024) {
        int i = base + tid;
        int v = (i < NN) ? g_cnt[i] : 0;
        if (i < NN) { g_dis[i] = rsqrtf(g_deg[i] + 1.0f); g_cnt[i] = 0; }
        int s = v;
#pragma unroll
        for (int d = 1; d < 32; d <<= 1) {
            int t = __shfl_up_sync(~0u, s, d);
            if (lane >= d) s += t;
        }
        if (lane == 31) wsum[w] = s;
        __syncthreads();
        if (w == 0) {
            int ws = wsum[lane];
#pragma unroll
            for (int d = 1; d < 32; d <<= 1) {
                int t = __shfl_up_sync(~0u, ws, d);
                if (lane >= d) ws += t;
            }
            wsum[lane] = ws;
        }
        __syncthreads();
        int off = choff + ((w > 0) ? wsum[w - 1] : 0);
        int total = wsum[31];
        if (i < NN) g_rowptr[i] = off + s - v;
        __syncthreads();
        if (tid == 0) choff += total;
        __syncthreads();
    }
    if (tid == 0) g_rowptr[NN] = choff;
}
__global__ void scatter_kernel(const int* __restrict__ ei, const float* __restrict__ ew) {
    int e = blockIdx.x * blockDim.x + threadIdx.x;
    if (e < EE) {
        int d = ei[EE + e];
        int s = ei[e];
        int pos = g_rowptr[d] + atomicAdd(&g_cnt[d], 1);
        float coef = g_dis[s] * ew[e] * g_dis[d];
        g_edge[pos] = ((ull)__float_as_uint(coef) << 32) | (unsigned)s;
    }
}

// ---------------- weight prepack: tconv fp16 hi/lo frag order + gcn transpose ----
__global__ void prep_w_kernel(const float* __restrict__ w0, const float* __restrict__ w1,
                              const float* __restrict__ w2, const float* __restrict__ w3,
                              const float* __restrict__ g1, const float* __restrict__ g2) {
    int v = blockIdx.x * 256 + threadIdx.x;
    if (v >= 29696) return;
    if (v >= 21504) {                       // GCN W transpose: wt[c*64+o] = W[o*64+c]
        int r = v - 21504;
        const float* g = (r < 4096) ? g1 : g2;
        int i = r & 4095;
        int c = i >> 6, o = i & 63;
        g_wt[r] = g[o * 64 + c];
        return;
    }
    const float* w; int C, off;
    if (v < 3072)       { w = w0; C = 32; off = 0; }
    else if (v < 9216)  { w = w1; C = 64; off = 3072; }
    else if (v < 15360) { w = w2; C = 64; off = 9216; }
    else                { w = w3; C = 64; off = 15360; }
    int r = v - off;
    int KS = C / 16;
    int lane = r & 31; r >>= 5;
    int wid = r & 7;  r >>= 3;
    int ks = r % KS;  r /= KS;
    int tap = r % 3;  r /= 3;
    int s = r;                               // 0 = hi, 1 = lo
    u32 o4[4];
#pragma unroll
    for (int rr = 0; rr < 4; rr++) {
        float vv[2];
#pragma unroll
        for (int b = 0; b < 2; b++) {
            int m_local = (rr & 1) * 8 + (lane >> 2);
            int k = (rr >> 1) * 8 + (lane & 3) * 2 + b;
            int hh = wid * 8 + (m_local & 7);
            int orig = (m_local < 8) ? hh : 64 + hh;
            int c = ks * 16 + k;
            float val = w[(size_t)orig * C * 3 + c * 3 + tap];
            float hi = __half2float(__float2half_rn(val));
            vv[b] = (s == 0) ? hi : (val - hi);
        }
        __half2 p = __floats2half2_rn(vv[0], vv[1]);
        o4[rr] = *(u32*)&p;
    }
    ((uint4*)g_wfrag)[v] = make_uint4(o4[0], o4[1], o4[2], o4[3]);
}

// ---------------- input transpose: [n][32][12] -> fp16 [n][12][32] ----------------
__global__ void transpose_x_kernel(const float* __restrict__ in, __half* __restrict__ oh) {
    int i = blockIdx.x * 256 + threadIdx.x;
    if (i < NN * 384) {
        int c = i & 31;
        int t = (i >> 5) % 12;
        int n = i / 384;
        oh[i] = __float2half_rn(in[n * 384 + c * 12 + t]);
    }
}

// ---------------- tensor-core gated temporal conv, fp16 2-term, cp.async DB ----
// xh: fp16 [col][C]; out fp32 [col][64] or fp16
template <int C, bool OUTH>
__global__ void __launch_bounds__(256, 2)
tconv_mma_kernel(const __half* __restrict__ xh, const uint4* __restrict__ wf,
                 const float* __restrict__ bias,
                 float* __restrict__ outf, __half* __restrict__ oh) {
    const int KS = C / 16;
    const int PAIRS = KS / 2;
    const int WST = C + 8;                 // smem row stride (fp16)
    const int BUFSZ = 66 * WST;            // one buffer, fp16 elems
    const int CHK = C / 8;                 // 16B chunks per row
    const int NCH = 66 * CHK;
    extern __shared__ __align__(16) __half sw[];
    const int tid = threadIdx.x;
    const int lane = tid & 31, wid = tid >> 5;
    u32 sb = smem_u32(sw);

    float bP = bias[wid * 8 + (lane >> 2)];
    float bQ = bias[64 + wid * 8 + (lane >> 2)];
    const int h = wid * 8 + (lane >> 2);
    const int lc = lane & 3;
    const int lq = lane >> 2;
    const int NT = TOTC / 64;

    auto stage = [&](int t, int bufsel) {
        int base = t * 64;
        for (int i = tid; i < NCH; i += 256) {
            int row = i / CHK, ch = i - row * CHK;
            int col = base - 1 + row;
            bool valid = (col >= 0 && col < TOTC);
            size_t cc = valid ? (size_t)col : 0;
            const __half* src = xh + cc * C + ch * 8;
            u32 dst = sb + (u32)((bufsel * BUFSZ + row * WST) * 2 + ch * 16);
            cp_async16(dst, src, valid);
        }
    };

    int t0 = blockIdx.x;
    if (t0 < NT) stage(t0, 0);
    CP_COMMIT();
    int sel = 0;

    for (int tile = t0; tile < NT; tile += gridDim.x) {
        int base = tile * 64;
        int nxt = tile + gridDim.x;
        if (nxt < NT) {
            stage(nxt, sel ^ 1);
            CP_COMMIT();
            CP_WAIT1();
        } else {
            CP_WAIT0();
        }
        __syncthreads();

        int m0[8], m2[8];
#pragma unroll
        for (int ns = 0; ns < 8; ns++) {
            int tm = (base + ns * 8 + lq) % 12;
            m0[ns] = (tm == 0);
            m2[ns] = (tm == 11);
        }

        float d[8][4];
#pragma unroll
        for (int ns = 0; ns < 8; ns++) { d[ns][0] = d[ns][1] = d[ns][2] = d[ns][3] = 0.f; }

        u32 bufbase = sb + (u32)(sel * BUFSZ * 2);

#pragma unroll
        for (int pair = 0; pair < PAIRS; pair++) {
            uint4 AH[3][2], AL[3][2];
#pragma unroll
            for (int tap = 0; tap < 3; tap++)
#pragma unroll
                for (int k2 = 0; k2 < 2; k2++) {
                    AH[tap][k2] = wf[((tap * KS + pair * 2 + k2) * 8 + wid) * 32 + lane];
                    AL[tap][k2] = wf[(((3 + tap) * KS + pair * 2 + k2) * 8 + wid) * 32 + lane];
                }
#pragma unroll
            for (int ns = 0; ns < 8; ns++) {
#pragma unroll
                for (int tap = 0; tap < 3; tap++) {
                    int row = ns * 8 + tap + (lane & 7);
                    int kk = pair * 32 + ((lane >> 3) & 3) * 8;
                    u32 a = bufbase + (u32)((row * WST + kk) * 2);
                    u32 b0, b1, b2, b3;
                    ldsm_x4(b0, b1, b2, b3, a);
                    if (tap == 0 && m0[ns]) { b0 = b1 = b2 = b3 = 0u; }
                    if (tap == 2 && m2[ns]) { b0 = b1 = b2 = b3 = 0u; }
                    mma16816(d[ns][0], d[ns][1], d[ns][2], d[ns][3],
                             AH[tap][0].x, AH[tap][0].y, AH[tap][0].z, AH[tap][0].w, b0, b1);
                    mma16816(d[ns][0], d[ns][1], d[ns][2], d[ns][3],
                             AL[tap][0].x, AL[tap][0].y, AL[tap][0].z, AL[tap][0].w, b0, b1);
                    mma16816(d[ns][0], d[ns][1], d[ns][2], d[ns][3],
                             AH[tap][1].x, AH[tap][1].y, AH[tap][1].z, AH[tap][1].w, b2, b3);
                    mma16816(d[ns][0], d[ns][1], d[ns][2], d[ns][3],
                             AL[tap][1].x, AL[tap][1].y, AL[tap][1].z, AL[tap][1].w, b2, b3);
                }
            }
        }

        // ---- epilogue: gate in-register (c0,c1)=P, (c2,c3)=Q of same h ----
#pragma unroll
        for (int ns = 0; ns < 8; ns++) {
            int col0 = base + ns * 8 + 2 * lc;
            float s2 = 1.f / (1.f + __expf(-(d[ns][2] + bQ)));
            float s3 = 1.f / (1.f + __expf(-(d[ns][3] + bQ)));
            float v0 = (d[ns][0] + bP) * s2;
            float v1 = (d[ns][1] + bP) * s3;
            if (OUTH) {
                oh[(size_t)col0 * 64 + h]       = __float2half_rn(v0);
                oh[(size_t)(col0 + 1) * 64 + h] = __float2half_rn(v1);
            } else {
                outf[(size_t)col0 * 64 + h]       = v0;
                outf[(size_t)(col0 + 1) * 64 + h] = v1;
            }
        }
        __syncthreads();
        sel ^= 1;
    }
}

// ---------------- fused GCN: gather + transform via L1-resident transposed W ----
__global__ void __launch_bounds__(192)
gcn_fused_kernel(const float* __restrict__ in, __half* __restrict__ oh,
                 const float* __restrict__ Wt, const float* __restrict__ bias) {
    __shared__ __align__(16) float xs[768];
    int n = blockIdx.x, tid = threadIdx.x;

    float d = g_dis[n];
    float d2 = d * d;
    float4 acc = ((const float4*)(in + (size_t)n * FEAT))[tid];
    acc.x *= d2; acc.y *= d2; acc.z *= d2; acc.w *= d2;

    int e = g_rowptr[n], e1 = g_rowptr[n + 1];
    for (; e + 8 <= e1; e += 8) {
        ull p[8]; float4 v[8];
#pragma unroll
        for (int j = 0; j < 8; j++) p[j] = g_edge[e + j];
#pragma unroll
        for (int j = 0; j < 8; j++)
            v[j] = ((const float4*)(in + (size_t)(int)(unsigned)p[j] * FEAT))[tid];
#pragma unroll
        for (int j = 0; j < 8; j++) {
            float cf = __uint_as_float((unsigned)(p[j] >> 32));
            acc.x += cf * v[j].x; acc.y += cf * v[j].y;
            acc.z += cf * v[j].z; acc.w += cf * v[j].w;
        }
    }
    for (; e + 2 <= e1; e += 2) {
        ull p0 = g_edge[e], p1 = g_edge[e + 1];
        float4 v0 = ((const float4*)(in + (size_t)(int)(unsigned)p0 * FEAT))[tid];
        float4 v1 = ((const float4*)(in + (size_t)(int)(unsigned)p1 * FEAT))[tid];
        float c0 = __uint_as_float((unsigned)(p0 >> 32));
        float c1 = __uint_as_float((unsigned)(p1 >> 32));
        acc.x += c0 * v0.x + c1 * v1.x;
        acc.y += c0 * v0.y + c1 * v1.y;
        acc.z += c0 * v0.z + c1 * v1.z;
        acc.w += c0 * v0.w + c1 * v1.w;
    }
    if (e < e1) {
        ull p = g_edge[e];
        float cf = __uint_as_float((unsigned)(p >> 32));
        float4 v = ((const float4*)(in + (size_t)(int)(unsigned)p * FEAT))[tid];
        acc.x += cf * v.x; acc.y += cf * v.y; acc.z += cf * v.z; acc.w += cf * v.w;
    }
    ((float4*)xs)[tid] = acc;
    __syncthreads();

    int o = tid & 63, tg = tid >> 6;
    float a0 = 0.f, a1 = 0.f, a2 = 0.f, a3 = 0.f;
    const float* xp = xs + tg * 256;
#pragma unroll 8
    for (int c = 0; c < 64; c++) {
        float wv = __ldg(Wt + c * 64 + o);
        a0 += wv * xp[c];
        a1 += wv * xp[64 + c];
        a2 += wv * xp[128 + c];
        a3 += wv * xp[192 + c];
    }
    float bv = bias[o];
    float rr[4] = {fmaxf(a0 + bv, 0.f), fmaxf(a1 + bv, 0.f),
                   fmaxf(a2 + bv, 0.f), fmaxf(a3 + bv, 0.f)};
#pragma unroll
    for (int i = 0; i < 4; i++) {
        size_t idx = (size_t)n * FEAT + (size_t)(tg * 4 + i) * 64 + o;
        oh[idx] = __float2half_rn(rr[i]);
    }
}

// ---------------- final conv (layout [n][t][c]) ----------------
__global__ void fin_kernel(const float* __restrict__ in, const float* __restrict__ w,
                           const float* __restrict__ b, float* __restrict__ out) {
    extern __shared__ float smf[];
    float* wt = smf;              // 12 rows, stride 772, reindexed [t*64+h]
    float* xt = smf + 12 * 772;   // 16 nodes, stride 772
    int tid = threadIdx.x;        // 192
    for (int i = tid; i < 12 * 768; i += 192) {
        int o = i / 768, r = i - o * 768;
        int t = r >> 6, hh = r & 63;
        wt[o * 772 + r] = w[o * 768 + hh * 12 + t];
    }
    int n0 = blockIdx.x * 16;
    for (int gi = tid; gi < 16 * 192; gi += 192) {
        int node = gi / 192, j = gi - node * 192;
        ((float4*)(xt + node * 772))[j] =
            ((const float4*)(in + (size_t)(n0 + node) * FEAT))[j];
    }
    __syncthreads();
    int node = tid / 12, o = tid - node * 12;
    const float* wr = wt + o * 772;
    const float* xr = xt + node * 772;
    float acc = 0.f;
#pragma unroll 4
    for (int j = 0; j < 192; j++) {
        float4 a = ((const float4*)wr)[j];
        float4 v = ((const float4*)xr)[j];
        acc += a.x * v.x + a.y * v.y + a.z * v.z + a.w * v.w;
    }
    out[(size_t)(n0 + node) * 12 + o] = acc + b[o];
}

// ---------------- launch ----------------
extern "C" void kernel_launch(void* const* d_in, const int* in_sizes, int n_in,
                              void* d_out, int out_size) {
    const float* x      = (const float*)d_in[0];
    const int*   ei     = (const int*)d_in[1];
    const float* ew     = (const float*)d_in[2];
    const float* tc1a_w = (const float*)d_in[3];
    const float* tc1a_b = (const float*)d_in[4];
    const float* gc1_w  = (const float*)d_in[5];
    const float* gc1_b  = (const float*)d_in[6];
    const float* tc1b_w = (const float*)d_in[7];
    const float* tc1b_b = (const float*)d_in[8];
    const float* tc2a_w = (const float*)d_in[9];
    const float* tc2a_b = (const float*)d_in[10];
    const float* gc2_w  = (const float*)d_in[11];
    const float* gc2_b  = (const float*)d_in[12];
    const float* tc2b_w = (const float*)d_in[13];
    const float* tc2b_b = (const float*)d_in[14];
    const float* fin_w  = (const float*)d_in[15];
    const float* fin_b  = (const float*)d_in[16];
    float* out = (float*)d_out;

    float *pA, *pB, *pWT; uint4* pW;
    __half *pH1, *pH2;
    cudaGetSymbolAddress((void**)&pA, g_bufA);
    cudaGetSymbolAddress((void**)&pB, g_bufB);
    cudaGetSymbolAddress((void**)&pW, g_wfrag);
    cudaGetSymbolAddress((void**)&pWT, g_wt);
    cudaGetSymbolAddress((void**)&pH1, g_h1);
    cudaGetSymbolAddress((void**)&pH2, g_h2);

    const int smem32 = 2 * 66 * 40 * 2;    // 10560
    const int smem64 = 2 * 66 * 72 * 2;    // 19008
    const int smemF  = (12 + 16) * 772 * 4;
    cudaFuncSetAttribute(fin_kernel, cudaFuncAttributeMaxDynamicSharedMemorySize, smemF);

    // ---- fork/join: CSR chain on a side stream, overlapped with prep+tc1a ----
    cudaStream_t s1;
    cudaStreamCreateWithFlags(&s1, cudaStreamNonBlocking);
    cudaEvent_t evFork, evJoin;
    cudaEventCreateWithFlags(&evFork, cudaEventDisableTiming);
    cudaEventCreateWithFlags(&evJoin, cudaEventDisableTiming);

    cudaEventRecord(evFork, 0);
    cudaStreamWaitEvent(s1, evFork, 0);

    zero_kernel<<<(NN + 255) / 256, 256, 0, s1>>>();
    prep_w_kernel<<<(29696 + 255) / 256, 256>>>(tc1a_w, tc1b_w, tc2a_w, tc2b_w, gc1_w, gc2_w);
    transpose_x_kernel<<<(NN * 384 + 255) / 256, 256>>>(x, pH1);
    // tc1a — ncu capture slot
    tconv_mma_kernel<32, false><<<296, 256, smem32>>>(pH1, pW, tc1a_b, pA, 0);
    hist_kernel<<<(EE + 255) / 256, 256, 0, s1>>>(ei, ew);
    scan_kernel<<<1, 1024, 0, s1>>>();
    scatter_kernel<<<(EE + 255) / 256, 256, 0, s1>>>(ei, ew);
    cudaEventRecord(evJoin, s1);
    cudaStreamWaitEvent(0, evJoin, 0);

    // gcn1: A -> H1
    gcn_fused_kernel<<<NN, 192>>>(pA, pH1, pWT, gc1_b);
    // tc1b: H1 -> H2
    tconv_mma_kernel<64, true><<<296, 256, smem64>>>(pH1, pW + 3072, tc1b_b, 0, pH2);
    // tc2a: H2 -> A fp32
    tconv_mma_kernel<64, false><<<296, 256, smem64>>>(pH2, pW + 9216, tc2a_b, pA, 0);
    // gcn2: A -> H1
    gcn_fused_kernel<<<NN, 192>>>(pA, pH1, pWT + 4096, gc2_b);
    // tc2b: H1 -> B fp32
    tconv_mma_kernel<64, false><<<296, 256, smem64>>>(pH1, pW + 15360, tc2b_b, pB, 0);
    // fin: B -> out
    fin_kernel<<<NN / 16, 192, smemF>>>(pB, fin_w, fin_b, out);
}